// round 12
// baseline (speedup 1.0000x reference)
#include <cuda_runtime.h>
#include <cuda_bf16.h>
#include <cstdint>

// Problem constants
#define BB 2
#define HH 16
#define SS 2048
#define DD 128
#define BH (BB*HH)

// ---------------------------------------------------------------------------
// Scratch: precomputed bf16 hi/lo splits (packed k-pairs in uint32 words)
// ---------------------------------------------------------------------------
__device__ uint32_t g_qh[(size_t)BH*SS*64];
__device__ uint32_t g_ql[(size_t)BH*SS*64];
__device__ uint32_t g_kh[(size_t)BH*SS*64];
__device__ uint32_t g_kl[(size_t)BH*SS*64];
__device__ uint32_t g_vth[(size_t)BH*DD*(SS/2)];
__device__ uint32_t g_vtl[(size_t)BH*DD*(SS/2)];

// ---------------------------------------------------------------------------
// Helpers
// ---------------------------------------------------------------------------
__device__ __forceinline__ uint32_t pack_bf16(__nv_bfloat16 lo16, __nv_bfloat16 hi16) {
    __nv_bfloat162 t; t.x = lo16; t.y = hi16;
    return *reinterpret_cast<uint32_t*>(&t);
}

__device__ __forceinline__ void cvt_pair(float x, float y, uint32_t& whi, uint32_t& wlo) {
    __nv_bfloat16 hx = __float2bfloat16_rn(x);
    __nv_bfloat16 hy = __float2bfloat16_rn(y);
    float fx = __bfloat162float(hx);
    float fy = __bfloat162float(hy);
    whi = pack_bf16(hx, hy);
    wlo = pack_bf16(__float2bfloat16_rn(x - fx), __float2bfloat16_rn(y - fy));
}

__device__ __forceinline__ uint32_t smaddr(const void* p) {
    return static_cast<uint32_t>(__cvta_generic_to_shared(p));
}

#define MMA16816(C, A, B0, B1)                                                  \
    asm volatile(                                                               \
        "mma.sync.aligned.m16n8k16.row.col.f32.bf16.bf16.f32 "                  \
        "{%0,%1,%2,%3}, {%4,%5,%6,%7}, {%8,%9}, {%0,%1,%2,%3};"                 \
        : "+f"((C)[0]), "+f"((C)[1]), "+f"((C)[2]), "+f"((C)[3])                \
        : "r"((A)[0]), "r"((A)[1]), "r"((A)[2]), "r"((A)[3]),                   \
          "r"(B0), "r"(B1))

__device__ __forceinline__ void ldsm4(uint32_t& r0, uint32_t& r1, uint32_t& r2,
                                      uint32_t& r3, uint32_t addr) {
    asm volatile("ldmatrix.sync.aligned.m8n8.x4.shared.b16 {%0,%1,%2,%3}, [%4];"
                 : "=r"(r0), "=r"(r1), "=r"(r2), "=r"(r3) : "r"(addr));
}

__device__ __forceinline__ void cp16(uint32_t s, const void* g) {
    asm volatile("cp.async.cg.shared.global [%0], [%1], 16;" :: "r"(s), "l"(g) : "memory");
}
#define CP_COMMIT asm volatile("cp.async.commit_group;" ::: "memory")
#define CP_WAIT1  asm volatile("cp.async.wait_group 1;" ::: "memory")
#define CP_WAIT0  asm volatile("cp.async.wait_group 0;" ::: "memory")

// ---------------------------------------------------------------------------
// Precompute 1: split Q (scaled) and K into bf16 hi/lo packed words
// ---------------------------------------------------------------------------
__global__ __launch_bounds__(256)
void split_qk_kernel(const float4* __restrict__ q, const float4* __restrict__ k)
{
    const float scl = 0.08838834764831845f;  // 1/sqrt(128)
    const size_t N4 = (size_t)BH * SS * (DD / 4);
    const size_t stride = (size_t)gridDim.x * blockDim.x;
    for (size_t i = (size_t)blockIdx.x * blockDim.x + threadIdx.x; i < N4; i += stride) {
        uint32_t h0, l0, h1, l1;
        float4 a = q[i];
        cvt_pair(a.x * scl, a.y * scl, h0, l0);
        cvt_pair(a.z * scl, a.w * scl, h1, l1);
        g_qh[2 * i] = h0; g_qh[2 * i + 1] = h1;
        g_ql[2 * i] = l0; g_ql[2 * i + 1] = l1;
        float4 c = k[i];
        cvt_pair(c.x, c.y, h0, l0);
        cvt_pair(c.z, c.w, h1, l1);
        g_kh[2 * i] = h0; g_kh[2 * i + 1] = h1;
        g_kl[2 * i] = l0; g_kl[2 * i + 1] = l1;
    }
}

// ---------------------------------------------------------------------------
// Precompute 2: V -> transposed split (k-major per head-dim row)
// ---------------------------------------------------------------------------
__global__ __launch_bounds__(256)
void split_vt_kernel(const float* __restrict__ v)
{
    __shared__ float tile[64][133];
    const int bh = blockIdx.y;
    const int s0 = blockIdx.x * 64;
    const int tid = threadIdx.x;
    const float* vb = v + (size_t)bh * SS * DD + (size_t)s0 * DD;

#pragma unroll
    for (int i = 0; i < 8; i++) {
        int idx = tid + i * 256;
        int r = idx >> 5, c4 = (idx & 31) * 4;
        float4 x = *reinterpret_cast<const float4*>(vb + (size_t)r * DD + c4);
        tile[r][c4 + 0] = x.x; tile[r][c4 + 1] = x.y;
        tile[r][c4 + 2] = x.z; tile[r][c4 + 3] = x.w;
    }
    __syncthreads();

    uint32_t* vh = g_vth + (size_t)bh * DD * (SS / 2) + (s0 >> 1);
    uint32_t* vl = g_vtl + (size_t)bh * DD * (SS / 2) + (s0 >> 1);
#pragma unroll
    for (int i = 0; i < 16; i++) {
        int idx = tid + i * 256;
        int d = idx >> 5, w = idx & 31;
        uint32_t hw_, lw_;
        cvt_pair(tile[2 * w][d], tile[2 * w + 1][d], hw_, lw_);
        vh[(size_t)d * (SS / 2) + w] = hw_;
        vl[(size_t)d * (SS / 2) + w] = lw_;
    }
}

// ---------------------------------------------------------------------------
// Fused kernel: scores (+bias, mask) + online softmax -> final attn
// Block = 128-row slab x all 2048 cols. Q slab resident in smem; K streamed
// in k16 chunks (2-stage cp.async). Writes unnormalized e, then pass-2
// normalize in place (L2-hot).
// grid = (16 slabs, 32 bh)
// ---------------------------------------------------------------------------
__global__ __launch_bounds__(256, 2)
void sdpa_fused_kernel(const int* __restrict__ mask, const float* __restrict__ bias,
                       float* __restrict__ attn)
{
    extern __shared__ uint32_t sm[];
    uint32_t (*Qh)[68]      = reinterpret_cast<uint32_t(*)[68]>(sm);            // 8704 w
    uint32_t (*Ql)[68]      = reinterpret_cast<uint32_t(*)[68]>(sm + 8704);     // 8704 w
    uint32_t (*Kh)[128][12] = reinterpret_cast<uint32_t(*)[128][12]>(sm + 17408); // 3072 w
    uint32_t (*Kl)[128][12] = reinterpret_cast<uint32_t(*)[128][12]>(sm + 20480); // 3072 w
    float* pm   = reinterpret_cast<float*>(sm + 23552);   // [2][128]
    float* ps   = reinterpret_cast<float*>(sm + 23808);   // [2][128]
    float* rowM = reinterpret_cast<float*>(sm + 24064);   // [128]
    float* rowS = reinterpret_cast<float*>(sm + 24192);   // [128]
    float (*hist)[128] = reinterpret_cast<float(*)[128]>(sm + 24320); // [16][128]

    const int tid  = threadIdx.x;
    const int warp = tid >> 5, lane = tid & 31;
    const int g = lane >> 2, t = lane & 3;
    const int wm = warp & 3, wn = warp >> 2;
    const int m_base = blockIdx.x * 128;
    const int bh = blockIdx.y, h = bh & 15, b = bh >> 4;

    const uint32_t* qh = g_qh + (size_t)bh * SS * 64;
    const uint32_t* ql = g_ql + (size_t)bh * SS * 64;
    const uint32_t* kh = g_kh + (size_t)bh * SS * 64;
    const uint32_t* kl = g_kl + (size_t)bh * SS * 64;
    const float* biasb = bias + (size_t)h * SS * SS;
    const int*   maskb = mask + (size_t)b * SS * SS;
    float*       attnb = attn + (size_t)bh * SS * SS;

    const int ro = ((lane >> 3) & 1) * 8 + (lane & 7);
    const int wo = (lane >> 4) * 4;

    if (tid < 128) { rowM[tid] = -INFINITY; rowS[tid] = 0.0f; }

    // Load Q slab (resident): 128 rows x 64 words, hi + lo
#pragma unroll
    for (int i = 0; i < 16; i++) {
        int idx = tid + i * 256;
        int row = idx >> 5, part = idx & 31;
        if (part < 16)
            cp16(smaddr(&Qh[row][part * 4]), qh + (size_t)(m_base + row) * 64 + part * 4);
        else
            cp16(smaddr(&Ql[row][(part - 16) * 4]), ql + (size_t)(m_base + row) * 64 + (part - 16) * 4);
    }

    auto load_k = [&](int st, int cc) {
        int ntc = cc >> 3, kcc = cc & 7;
        const uint32_t* khb = kh + (size_t)(ntc * 128) * 64 + kcc * 8;
        const uint32_t* klb = kl + (size_t)(ntc * 128) * 64 + kcc * 8;
#pragma unroll
        for (int i = 0; i < 2; i++) {
            int idx = tid + i * 256;
            int row = idx >> 2, part = idx & 3;
            if (part < 2)
                cp16(smaddr(&Kh[st][row][part * 4]), khb + (size_t)row * 64 + part * 4);
            else
                cp16(smaddr(&Kl[st][row][(part - 2) * 4]), klb + (size_t)row * 64 + (part - 2) * 4);
        }
    };

    load_k(0, 0);
    CP_COMMIT;

    float acc[2][8][4];
#pragma unroll
    for (int i = 0; i < 2; i++)
#pragma unroll
        for (int j = 0; j < 8; j++)
#pragma unroll
            for (int c = 0; c < 4; c++) acc[i][j][c] = 0.0f;

#pragma unroll 1
    for (int nt = 0; nt < 16; nt++) {
#pragma unroll 1
        for (int kc = 0; kc < 8; kc++) {
            const int cc = nt * 8 + kc;
            const int C = cc & 1;
            if (cc < 127) load_k(C ^ 1, cc + 1);
            CP_COMMIT;
            if (cc < 127) { CP_WAIT1; } else { CP_WAIT0; }
            __syncthreads();

            const int koff = kc * 8;
            uint32_t ah[2][4], al[2][4];
#pragma unroll
            for (int mt = 0; mt < 2; mt++) {
                int r = wm * 32 + mt * 16 + ro;
                ldsm4(ah[mt][0], ah[mt][1], ah[mt][2], ah[mt][3], smaddr(&Qh[r][koff + wo]));
                ldsm4(al[mt][0], al[mt][1], al[mt][2], al[mt][3], smaddr(&Ql[r][koff + wo]));
            }
#pragma unroll
            for (int np = 0; np < 4; np++) {
                int nr = wn * 64 + np * 16 + ro;
                uint32_t b0, b1, b2, b3, c0, c1, c2, c3;
                ldsm4(b0, b1, b2, b3, smaddr(&Kh[C][nr][wo]));
                ldsm4(c0, c1, c2, c3, smaddr(&Kl[C][nr][wo]));
#pragma unroll
                for (int mt = 0; mt < 2; mt++) {
                    MMA16816(acc[mt][np * 2],     ah[mt], b0, b2);
                    MMA16816(acc[mt][np * 2],     ah[mt], c0, c2);
                    MMA16816(acc[mt][np * 2],     al[mt], b0, b2);
                    MMA16816(acc[mt][np * 2 + 1], ah[mt], b1, b3);
                    MMA16816(acc[mt][np * 2 + 1], ah[mt], c1, c3);
                    MMA16816(acc[mt][np * 2 + 1], al[mt], b1, b3);
                }
            }
            __syncthreads();
        }

        // ---- tile epilogue: bias+mask, online softmax stats, write e ----
        float vmax[4] = {-INFINITY, -INFINITY, -INFINITY, -INFINITY};
#pragma unroll
        for (int mt = 0; mt < 2; mt++)
#pragma unroll
            for (int n8 = 0; n8 < 8; n8++) {
                int col = nt * 128 + wn * 64 + n8 * 8 + 2 * t;
#pragma unroll
                for (int half = 0; half < 2; half++) {
                    int row = m_base + wm * 32 + mt * 16 + g + half * 8;
                    float2 bb = *reinterpret_cast<const float2*>(biasb + (size_t)row * SS + col);
                    int2   mm = *reinterpret_cast<const int2*>(maskb + (size_t)row * SS + col);
                    float s0 = acc[mt][n8][half * 2]     + bb.x;
                    float s1 = acc[mt][n8][half * 2 + 1] + bb.y;
                    if (mm.x == 0) s0 = -1e9f;
                    if (mm.y == 0) s1 = -1e9f;
                    acc[mt][n8][half * 2]     = s0;
                    acc[mt][n8][half * 2 + 1] = s1;
                    int vi = mt * 2 + half;
                    vmax[vi] = fmaxf(vmax[vi], fmaxf(s0, s1));
                }
            }
#pragma unroll
        for (int vi = 0; vi < 4; vi++) {
            float vm = vmax[vi];
            vm = fmaxf(vm, __shfl_xor_sync(0xFFFFFFFFu, vm, 1));
            vm = fmaxf(vm, __shfl_xor_sync(0xFFFFFFFFu, vm, 2));
            vmax[vi] = vm;
        }
        if (t == 0) {
#pragma unroll
            for (int vi = 0; vi < 4; vi++) {
                int mt = vi >> 1, half = vi & 1;
                pm[wn * 128 + wm * 32 + mt * 16 + g + half * 8] = vmax[vi];
            }
        }
        __syncthreads();

        float mnew[4];
#pragma unroll
        for (int vi = 0; vi < 4; vi++) {
            int mt = vi >> 1, half = vi & 1;
            int rl = wm * 32 + mt * 16 + g + half * 8;
            mnew[vi] = fmaxf(rowM[rl], fmaxf(pm[rl], pm[128 + rl]));
        }

        float vsum[4] = {0.f, 0.f, 0.f, 0.f};
#pragma unroll
        for (int mt = 0; mt < 2; mt++)
#pragma unroll
            for (int n8 = 0; n8 < 8; n8++) {
                int col = nt * 128 + wn * 64 + n8 * 8 + 2 * t;
#pragma unroll
                for (int half = 0; half < 2; half++) {
                    int row = m_base + wm * 32 + mt * 16 + g + half * 8;
                    int vi = mt * 2 + half;
                    float e0 = __expf(acc[mt][n8][half * 2]     - mnew[vi]);
                    float e1 = __expf(acc[mt][n8][half * 2 + 1] - mnew[vi]);
                    *reinterpret_cast<float2*>(attnb + (size_t)row * SS + col) = make_float2(e0, e1);
                    vsum[vi] += e0 + e1;
                }
            }
#pragma unroll
        for (int vi = 0; vi < 4; vi++) {
            float s = vsum[vi];
            s += __shfl_xor_sync(0xFFFFFFFFu, s, 1);
            s += __shfl_xor_sync(0xFFFFFFFFu, s, 2);
            vsum[vi] = s;
        }
        if (t == 0) {
#pragma unroll
            for (int vi = 0; vi < 4; vi++) {
                int mt = vi >> 1, half = vi & 1;
                ps[wn * 128 + wm * 32 + mt * 16 + g + half * 8] = vsum[vi];
            }
        }
        __syncthreads();
        if (warp < 4 && t == 0) {
#pragma unroll
            for (int vi = 0; vi < 4; vi++) {
                int mt = vi >> 1, half = vi & 1;
                int rl = wm * 32 + mt * 16 + g + half * 8;
                float mo = rowM[rl], mn = mnew[vi];
                float S = rowS[rl] * __expf(mo - mn) + ps[rl] + ps[128 + rl];
                rowS[rl] = S; rowM[rl] = mn; hist[nt][rl] = mn;
            }
        }
        __syncthreads();
#pragma unroll
        for (int i = 0; i < 2; i++)
#pragma unroll
            for (int j = 0; j < 8; j++)
#pragma unroll
                for (int c = 0; c < 4; c++) acc[i][j][c] = 0.0f;
    }

    // ---- pass 2: per-(tile,row) correction, normalize in place (L2-hot) ----
    for (int i = tid; i < 16 * 128; i += 256) {
        int ntc = i >> 7, rl = i & 127;
        hist[ntc][rl] = __expf(hist[ntc][rl] - rowM[rl]) * (1.0f / rowS[rl]);
    }
    __syncthreads();

    float4* ap = reinterpret_cast<float4*>(attnb + (size_t)m_base * SS);
#pragma unroll 4
    for (int i = 0; i < 256; i++) {
        int idx = tid + i * 256;
        int rl = idx >> 9, c4 = idx & 511;
        float c = hist[c4 >> 5][rl];
        float4 x = ap[(size_t)rl * 512 + c4];
        x.x *= c; x.y *= c; x.z *= c; x.w *= c;
        ap[(size_t)rl * 512 + c4] = x;
    }
}

// ---------------------------------------------------------------------------
// Kernel 3: out = attn @ V. 128 rows x 128 cols, K=2048, k-chunk=32.
// ---------------------------------------------------------------------------
__global__ __launch_bounds__(256, 2)
void sdpa_out2_kernel(const float* __restrict__ attn, float* __restrict__ out)
{
    extern __shared__ uint32_t sm[];
    float    (*Ar)[128][36] = reinterpret_cast<float(*)[128][36]>(sm);
    uint32_t (*Ah)[20]      = reinterpret_cast<uint32_t(*)[20]>(sm + 9216);
    uint32_t (*Al)[20]      = reinterpret_cast<uint32_t(*)[20]>(sm + 11776);
    uint32_t (*Bh)[128][20] = reinterpret_cast<uint32_t(*)[128][20]>(sm + 14336);
    uint32_t (*Bl)[128][20] = reinterpret_cast<uint32_t(*)[128][20]>(sm + 19456);

    const int tid  = threadIdx.x;
    const int warp = tid >> 5, lane = tid & 31;
    const int g = lane >> 2, t = lane & 3;
    const int wm = warp & 3, wn = warp >> 2;
    const int bh = blockIdx.z;
    const int m_base = blockIdx.y * 128;

    const float* ab = attn + (size_t)bh * SS * SS;
    const uint32_t* vh = g_vth + (size_t)bh * DD * (SS / 2);
    const uint32_t* vl = g_vtl + (size_t)bh * DD * (SS / 2);

    const int ro = ((lane >> 3) & 1) * 8 + (lane & 7);
    const int wo = (lane >> 4) * 4;

    float acc[2][8][4];
#pragma unroll
    for (int i = 0; i < 2; i++)
#pragma unroll
        for (int j = 0; j < 8; j++)
#pragma unroll
            for (int c = 0; c < 4; c++) acc[i][j][c] = 0.0f;

    auto load_stage = [&](int st, int kc) {
#pragma unroll
        for (int i = 0; i < 4; i++) {
            int idx = tid + i * 256;
            int row = idx >> 3, f4 = (idx & 7) * 4;
            cp16(smaddr(&Ar[st][row][f4]), ab + (size_t)(m_base + row) * SS + kc * 32 + f4);
        }
#pragma unroll
        for (int i = 0; i < 2; i++) {
            int idx = tid + i * 256;
            int d = idx >> 2, q4 = (idx & 3) * 4;
            cp16(smaddr(&Bh[st][d][q4]), vh + (size_t)d * (SS / 2) + kc * 16 + q4);
            cp16(smaddr(&Bl[st][d][q4]), vl + (size_t)d * (SS / 2) + kc * 16 + q4);
        }
    };

    load_stage(0, 0);
    CP_COMMIT;

#pragma unroll 1
    for (int kc = 0; kc < 64; kc++) {
        const int C = kc & 1;
        if (kc < 63) load_stage(C ^ 1, kc + 1);
        CP_COMMIT;
        if (kc < 63) { CP_WAIT1; } else { CP_WAIT0; }
        __syncthreads();

#pragma unroll
        for (int i = 0; i < 4; i++) {
            int idx = tid + i * 256;
            int row = idx >> 3, f4 = idx & 7;
            float4 x = *reinterpret_cast<const float4*>(&Ar[C][row][f4 * 4]);
            uint32_t h0, l0, h1, l1;
            cvt_pair(x.x, x.y, h0, l0);
            cvt_pair(x.z, x.w, h1, l1);
            uint2 hh; hh.x = h0; hh.y = h1;
            uint2 ll; ll.x = l0; ll.y = l1;
            *reinterpret_cast<uint2*>(&Ah[row][f4 * 2]) = hh;
            *reinterpret_cast<uint2*>(&Al[row][f4 * 2]) = ll;
        }
        __syncthreads();

#pragma unroll
        for (int ks = 0; ks < 2; ks++) {
            const int ko = ks * 8;
            uint32_t ah[2][4], al[2][4];
#pragma unroll
            for (int mt = 0; mt < 2; mt++) {
                int r = wm * 32 + mt * 16 + ro;
                ldsm4(ah[mt][0], ah[mt][1], ah[mt][2], ah[mt][3], smaddr(&Ah[r][ko + wo]));
                ldsm4(al[mt][0], al[mt][1], al[mt][2], al[mt][3], smaddr(&Al[r][ko + wo]));
            }
#pragma unroll
            for (int np = 0; np < 4; np++) {
                int nr = wn * 64 + np * 16 + ro;
                uint32_t b0, b1, b2, b3, c0, c1, c2, c3;
                ldsm4(b0, b1, b2, b3, smaddr(&Bh[C][nr][ko + wo]));
                ldsm4(c0, c1, c2, c3, smaddr(&Bl[C][nr][ko + wo]));
#pragma unroll
                for (int mt = 0; mt < 2; mt++) {
                    MMA16816(acc[mt][np * 2],     ah[mt], b0, b2);
                    MMA16816(acc[mt][np * 2],     ah[mt], c0, c2);
                    MMA16816(acc[mt][np * 2],     al[mt], b0, b2);
                    MMA16816(acc[mt][np * 2 + 1], ah[mt], b1, b3);
                    MMA16816(acc[mt][np * 2 + 1], ah[mt], c1, c3);
                    MMA16816(acc[mt][np * 2 + 1], al[mt], b1, b3);
                }
            }
        }
        __syncthreads();
    }

    float* ob = out + (size_t)bh * SS * DD;
#pragma unroll
    for (int mt = 0; mt < 2; mt++) {
#pragma unroll
        for (int nt = 0; nt < 8; nt++) {
            int col  = wn * 64 + nt * 8 + 2 * t;
            int row0 = m_base + wm * 32 + mt * 16 + g;
#pragma unroll
            for (int half = 0; half < 2; half++) {
                int row = row0 + half * 8;
                *reinterpret_cast<float2*>(ob + (size_t)row * DD + col) =
                    make_float2(acc[mt][nt][half * 2], acc[mt][nt][half * 2 + 1]);
            }
        }
    }
}

// ---------------------------------------------------------------------------
// Launch
// ---------------------------------------------------------------------------
extern "C" void kernel_launch(void* const* d_in, const int* in_sizes, int n_in,
                              void* d_out, int out_size)
{
    const float* q    = (const float*)d_in[0];
    const float* k    = (const float*)d_in[1];
    const float* v    = (const float*)d_in[2];
    const int*   mask = (const int*)  d_in[3];
    const float* bias = (const float*)d_in[4];

    float* out  = (float*)d_out;                       // [B,H,S,D]
    float* attn = out + (size_t)BB * HH * SS * DD;     // [B,H,S,S]

    cudaFuncSetAttribute(sdpa_fused_kernel,
                         cudaFuncAttributeMaxDynamicSharedMemorySize, 105472);
    cudaFuncSetAttribute(sdpa_out2_kernel,
                         cudaFuncAttributeMaxDynamicSharedMemorySize, 98304);

    split_qk_kernel<<<2048, 256>>>((const float4*)q, (const float4*)k);
    split_vt_kernel<<<dim3(SS / 64, BH), 256>>>(v);

    dim3 g1(SS / 128, BH);
    sdpa_fused_kernel<<<g1, 256, 105472>>>(mask, bias, attn);

    dim3 g3(1, SS / 128, BH);
    sdpa_out2_kernel<<<g3, 256, 98304>>>(attn, out);
}

// round 14
// speedup vs baseline: 1.2262x; 1.2262x over previous
#include <cuda_runtime.h>
#include <cuda_bf16.h>
#include <cstdint>

// Problem constants
#define BB 2
#define HH 16
#define SS 2048
#define DD 128
#define BH (BB*HH)

// ---------------------------------------------------------------------------
// Scratch: precomputed bf16 hi/lo splits (packed k-pairs in uint32 words)
//   g_qh/g_ql, g_kh/g_kl : [bh][s][64 words]   (q pre-scaled by 1/sqrt(D))
//   g_vth/g_vtl          : [bh][d][1024 words] (V transposed, k-major)
//   g_ah/g_al            : [row][1024 words]   (normalized attn split)
// ---------------------------------------------------------------------------
__device__ uint32_t g_qh[(size_t)BH*SS*64];
__device__ uint32_t g_ql[(size_t)BH*SS*64];
__device__ uint32_t g_kh[(size_t)BH*SS*64];
__device__ uint32_t g_kl[(size_t)BH*SS*64];
__device__ uint32_t g_vth[(size_t)BH*DD*(SS/2)];
__device__ uint32_t g_vtl[(size_t)BH*DD*(SS/2)];
__device__ uint32_t g_ah[(size_t)BH*SS*(SS/2)];
__device__ uint32_t g_al[(size_t)BH*SS*(SS/2)];

// ---------------------------------------------------------------------------
// Helpers
// ---------------------------------------------------------------------------
__device__ __forceinline__ uint32_t pack_bf16(__nv_bfloat16 lo16, __nv_bfloat16 hi16) {
    __nv_bfloat162 t; t.x = lo16; t.y = hi16;
    return *reinterpret_cast<uint32_t*>(&t);
}

__device__ __forceinline__ void cvt_pair(float x, float y, uint32_t& whi, uint32_t& wlo) {
    __nv_bfloat16 hx = __float2bfloat16_rn(x);
    __nv_bfloat16 hy = __float2bfloat16_rn(y);
    float fx = __bfloat162float(hx);
    float fy = __bfloat162float(hy);
    whi = pack_bf16(hx, hy);
    wlo = pack_bf16(__float2bfloat16_rn(x - fx), __float2bfloat16_rn(y - fy));
}

__device__ __forceinline__ uint32_t smaddr(const void* p) {
    return static_cast<uint32_t>(__cvta_generic_to_shared(p));
}

#define MMA16816(C, A, B0, B1)                                                  \
    asm volatile(                                                               \
        "mma.sync.aligned.m16n8k16.row.col.f32.bf16.bf16.f32 "                  \
        "{%0,%1,%2,%3}, {%4,%5,%6,%7}, {%8,%9}, {%0,%1,%2,%3};"                 \
        : "+f"((C)[0]), "+f"((C)[1]), "+f"((C)[2]), "+f"((C)[3])                \
        : "r"((A)[0]), "r"((A)[1]), "r"((A)[2]), "r"((A)[3]),                   \
          "r"(B0), "r"(B1))

__device__ __forceinline__ void ldsm4(uint32_t& r0, uint32_t& r1, uint32_t& r2,
                                      uint32_t& r3, uint32_t addr) {
    asm volatile("ldmatrix.sync.aligned.m8n8.x4.shared.b16 {%0,%1,%2,%3}, [%4];"
                 : "=r"(r0), "=r"(r1), "=r"(r2), "=r"(r3) : "r"(addr));
}

__device__ __forceinline__ void cp16(uint32_t s, const void* g) {
    asm volatile("cp.async.cg.shared.global [%0], [%1], 16;" :: "r"(s), "l"(g) : "memory");
}
#define CP_COMMIT asm volatile("cp.async.commit_group;" ::: "memory")
#define CP_WAIT1  asm volatile("cp.async.wait_group 1;" ::: "memory")
#define CP_WAIT0  asm volatile("cp.async.wait_group 0;" ::: "memory")

// ---------------------------------------------------------------------------
// Precompute 1: split Q (scaled) and K into bf16 hi/lo packed words
// ---------------------------------------------------------------------------
__global__ __launch_bounds__(256)
void split_qk_kernel(const float4* __restrict__ q, const float4* __restrict__ k)
{
    const float scl = 0.08838834764831845f;  // 1/sqrt(128)
    const size_t N4 = (size_t)BH * SS * (DD / 4);
    const size_t stride = (size_t)gridDim.x * blockDim.x;
    for (size_t i = (size_t)blockIdx.x * blockDim.x + threadIdx.x; i < N4; i += stride) {
        uint32_t h0, l0, h1, l1;
        float4 a = q[i];
        cvt_pair(a.x * scl, a.y * scl, h0, l0);
        cvt_pair(a.z * scl, a.w * scl, h1, l1);
        g_qh[2 * i] = h0; g_qh[2 * i + 1] = h1;
        g_ql[2 * i] = l0; g_ql[2 * i + 1] = l1;
        float4 c = k[i];
        cvt_pair(c.x, c.y, h0, l0);
        cvt_pair(c.z, c.w, h1, l1);
        g_kh[2 * i] = h0; g_kh[2 * i + 1] = h1;
        g_kl[2 * i] = l0; g_kl[2 * i + 1] = l1;
    }
}

// ---------------------------------------------------------------------------
// Precompute 2: V -> transposed split (k-major per head-dim row)
// ---------------------------------------------------------------------------
__global__ __launch_bounds__(256)
void split_vt_kernel(const float* __restrict__ v)
{
    __shared__ float tile[64][133];
    const int bh = blockIdx.y;
    const int s0 = blockIdx.x * 64;
    const int tid = threadIdx.x;
    const float* vb = v + (size_t)bh * SS * DD + (size_t)s0 * DD;

#pragma unroll
    for (int i = 0; i < 8; i++) {
        int idx = tid + i * 256;
        int r = idx >> 5, c4 = (idx & 31) * 4;
        float4 x = *reinterpret_cast<const float4*>(vb + (size_t)r * DD + c4);
        tile[r][c4 + 0] = x.x; tile[r][c4 + 1] = x.y;
        tile[r][c4 + 2] = x.z; tile[r][c4 + 3] = x.w;
    }
    __syncthreads();

    uint32_t* vh = g_vth + (size_t)bh * DD * (SS / 2) + (s0 >> 1);
    uint32_t* vl = g_vtl + (size_t)bh * DD * (SS / 2) + (s0 >> 1);
#pragma unroll
    for (int i = 0; i < 16; i++) {
        int idx = tid + i * 256;
        int d = idx >> 5, w = idx & 31;
        uint32_t hw_, lw_;
        cvt_pair(tile[2 * w][d], tile[2 * w + 1][d], hw_, lw_);
        vh[(size_t)d * (SS / 2) + w] = hw_;
        vl[(size_t)d * (SS / 2) + w] = lw_;
    }
}

// ---------------------------------------------------------------------------
// Kernel 1: raw masked scores -> attn buffer
// 128x128 tile, 256 threads, k-chunk=32, 2-stage cp.async pipeline, ldmatrix.
// ---------------------------------------------------------------------------
__global__ __launch_bounds__(256, 2)
void sdpa_scores2_kernel(const int* __restrict__ mask, const float* __restrict__ bias,
                         float* __restrict__ attn)
{
    extern __shared__ uint32_t sm[];
    uint32_t (*Qh)[128][20] = reinterpret_cast<uint32_t(*)[128][20]>(sm);
    uint32_t (*Ql)[128][20] = reinterpret_cast<uint32_t(*)[128][20]>(sm + 5120);
    uint32_t (*Kh)[128][20] = reinterpret_cast<uint32_t(*)[128][20]>(sm + 10240);
    uint32_t (*Kl)[128][20] = reinterpret_cast<uint32_t(*)[128][20]>(sm + 15360);

    const int tid  = threadIdx.x;
    const int warp = tid >> 5, lane = tid & 31;
    const int g = lane >> 2, t = lane & 3;
    const int wm = warp & 3, wn = warp >> 2;
    const int z = blockIdx.z, h = z >> 1, b = z & 1, bh = b * HH + h;
    const int m_base = blockIdx.y * 128;
    const int n_base = blockIdx.x * 128;

    const uint32_t* qh = g_qh + (size_t)bh * SS * 64;
    const uint32_t* ql = g_ql + (size_t)bh * SS * 64;
    const uint32_t* kh = g_kh + (size_t)bh * SS * 64;
    const uint32_t* kl = g_kl + (size_t)bh * SS * 64;

    const int ro = ((lane >> 3) & 1) * 8 + (lane & 7);
    const int wo = (lane >> 4) * 4;

    float acc[2][8][4];
#pragma unroll
    for (int i = 0; i < 2; i++)
#pragma unroll
        for (int j = 0; j < 8; j++)
#pragma unroll
            for (int c = 0; c < 4; c++) acc[i][j][c] = 0.0f;

    auto load_stage = [&](int st, int kc) {
        const int w0 = kc * 16;
#pragma unroll
        for (int i = 0; i < 2; i++) {
            int idx = tid + i * 256;
            int row = idx >> 2, q4 = (idx & 3) * 4;
            cp16(smaddr(&Qh[st][row][q4]), qh + (size_t)(m_base + row) * 64 + w0 + q4);
            cp16(smaddr(&Ql[st][row][q4]), ql + (size_t)(m_base + row) * 64 + w0 + q4);
            cp16(smaddr(&Kh[st][row][q4]), kh + (size_t)(n_base + row) * 64 + w0 + q4);
            cp16(smaddr(&Kl[st][row][q4]), kl + (size_t)(n_base + row) * 64 + w0 + q4);
        }
    };

    load_stage(0, 0);
    CP_COMMIT;

#pragma unroll 1
    for (int kc = 0; kc < 4; kc++) {
        const int C = kc & 1;
        if (kc < 3) load_stage(C ^ 1, kc + 1);
        CP_COMMIT;
        if (kc < 3) { CP_WAIT1; } else { CP_WAIT0; }
        __syncthreads();

#pragma unroll
        for (int ks = 0; ks < 2; ks++) {
            const int ko = ks * 8;
            uint32_t ah[2][4], al[2][4];
#pragma unroll
            for (int mt = 0; mt < 2; mt++) {
                int r = wm * 32 + mt * 16 + ro;
                ldsm4(ah[mt][0], ah[mt][1], ah[mt][2], ah[mt][3], smaddr(&Qh[C][r][ko + wo]));
                ldsm4(al[mt][0], al[mt][1], al[mt][2], al[mt][3], smaddr(&Ql[C][r][ko + wo]));
            }
#pragma unroll
            for (int np = 0; np < 4; np++) {
                int nr = wn * 64 + np * 16 + ro;
                uint32_t b0, b1, b2, b3, c0, c1, c2, c3;
                ldsm4(b0, b1, b2, b3, smaddr(&Kh[C][nr][ko + wo]));
                ldsm4(c0, c1, c2, c3, smaddr(&Kl[C][nr][ko + wo]));
#pragma unroll
                for (int mt = 0; mt < 2; mt++) {
                    MMA16816(acc[mt][np * 2],     ah[mt], b0, b2);
                    MMA16816(acc[mt][np * 2],     ah[mt], c0, c2);
                    MMA16816(acc[mt][np * 2],     al[mt], b0, b2);
                    MMA16816(acc[mt][np * 2 + 1], ah[mt], b1, b3);
                    MMA16816(acc[mt][np * 2 + 1], ah[mt], c1, c3);
                    MMA16816(acc[mt][np * 2 + 1], al[mt], b1, b3);
                }
            }
        }
        __syncthreads();
    }

    // --- epilogue: + bias, mask, write raw scores (q was pre-scaled) ---
    const float* biasb = bias + (size_t)h * SS * SS;
    const int*   maskb = mask + (size_t)b * SS * SS;
    float*       attnb = attn + (size_t)bh * SS * SS;

#pragma unroll
    for (int mt = 0; mt < 2; mt++) {
#pragma unroll
        for (int nt = 0; nt < 8; nt++) {
            int col  = n_base + wn * 64 + nt * 8 + 2 * t;
            int row0 = m_base + wm * 32 + mt * 16 + g;
#pragma unroll
            for (int half = 0; half < 2; half++) {
                int row = row0 + half * 8;
                float2 bb = *reinterpret_cast<const float2*>(biasb + (size_t)row * SS + col);
                int2   mm = *reinterpret_cast<const int2*>(maskb + (size_t)row * SS + col);
                float s0 = acc[mt][nt][half * 2 + 0] + bb.x;
                float s1 = acc[mt][nt][half * 2 + 1] + bb.y;
                if (mm.x == 0) s0 = -1e9f;
                if (mm.y == 0) s1 = -1e9f;
                *reinterpret_cast<float2*>(attnb + (size_t)row * SS + col) = make_float2(s0, s1);
            }
        }
    }
}

// ---------------------------------------------------------------------------
// Kernel 2: row softmax, in-place; ALSO emits normalized attn as bf16 hi/lo
// split (packed k-pair words) for the out kernel.
// ---------------------------------------------------------------------------
__global__ __launch_bounds__(256)
void sdpa_softmax_kernel(float* __restrict__ attn)
{
    const size_t row = blockIdx.x;
    float4* p = reinterpret_cast<float4*>(attn + row * SS);
    const int tid = threadIdx.x;
    const int lane = tid & 31, wid = tid >> 5;

    float4 v1 = p[tid];
    float4 v2 = p[tid + 256];

    float m = fmaxf(fmaxf(fmaxf(v1.x, v1.y), fmaxf(v1.z, v1.w)),
                    fmaxf(fmaxf(v2.x, v2.y), fmaxf(v2.z, v2.w)));
#pragma unroll
    for (int o = 16; o > 0; o >>= 1) m = fmaxf(m, __shfl_xor_sync(0xFFFFFFFFu, m, o));

    __shared__ float rmax[8], rsum[8];
    if (lane == 0) rmax[wid] = m;
    __syncthreads();
    m = rmax[0];
#pragma unroll
    for (int j = 1; j < 8; j++) m = fmaxf(m, rmax[j]);

    float e0 = __expf(v1.x - m), e1 = __expf(v1.y - m);
    float e2 = __expf(v1.z - m), e3 = __expf(v1.w - m);
    float e4 = __expf(v2.x - m), e5 = __expf(v2.y - m);
    float e6 = __expf(v2.z - m), e7 = __expf(v2.w - m);

    float s = (e0 + e1) + (e2 + e3) + (e4 + e5) + (e6 + e7);
#pragma unroll
    for (int o = 16; o > 0; o >>= 1) s += __shfl_xor_sync(0xFFFFFFFFu, s, o);
    if (lane == 0) rsum[wid] = s;
    __syncthreads();
    s = rsum[0];
#pragma unroll
    for (int j = 1; j < 8; j++) s += rsum[j];

    float inv = 1.0f / s;
    float4 r1 = make_float4(e0 * inv, e1 * inv, e2 * inv, e3 * inv);
    float4 r2 = make_float4(e4 * inv, e5 * inv, e6 * inv, e7 * inv);
    p[tid]       = r1;
    p[tid + 256] = r2;

    // split write for the out kernel (words = packed k-pairs, col/2)
    uint32_t* ah = g_ah + row * (SS / 2);
    uint32_t* al = g_al + row * (SS / 2);
    uint32_t h0, l0, h1, l1;
    cvt_pair(r1.x, r1.y, h0, l0);
    cvt_pair(r1.z, r1.w, h1, l1);
    *reinterpret_cast<uint2*>(ah + tid * 2) = make_uint2(h0, h1);
    *reinterpret_cast<uint2*>(al + tid * 2) = make_uint2(l0, l1);
    cvt_pair(r2.x, r2.y, h0, l0);
    cvt_pair(r2.z, r2.w, h1, l1);
    *reinterpret_cast<uint2*>(ah + 512 + tid * 2) = make_uint2(h0, h1);
    *reinterpret_cast<uint2*>(al + 512 + tid * 2) = make_uint2(l0, l1);
}

// ---------------------------------------------------------------------------
// Kernel 3: out = attn @ V. 128 rows x 128 cols, K=2048, k-chunk=32.
// Both operands pre-split in global: cp.async straight into LDSM layout,
// zero in-loop conversion, one load phase + one compute phase per chunk.
// ---------------------------------------------------------------------------
__global__ __launch_bounds__(256, 2)
void sdpa_out3_kernel(float* __restrict__ out)
{
    extern __shared__ uint32_t sm[];
    uint32_t (*Ah)[128][20] = reinterpret_cast<uint32_t(*)[128][20]>(sm);          // 5120 w
    uint32_t (*Al)[128][20] = reinterpret_cast<uint32_t(*)[128][20]>(sm + 5120);
    uint32_t (*Bh)[128][20] = reinterpret_cast<uint32_t(*)[128][20]>(sm + 10240);
    uint32_t (*Bl)[128][20] = reinterpret_cast<uint32_t(*)[128][20]>(sm + 15360);

    const int tid  = threadIdx.x;
    const int warp = tid >> 5, lane = tid & 31;
    const int g = lane >> 2, t = lane & 3;
    const int wm = warp & 3, wn = warp >> 2;
    const int bh = blockIdx.z;
    const int m_base = blockIdx.y * 128;

    const uint32_t* ahb = g_ah + ((size_t)bh * SS + m_base) * (SS / 2);
    const uint32_t* alb = g_al + ((size_t)bh * SS + m_base) * (SS / 2);
    const uint32_t* vhb = g_vth + (size_t)bh * DD * (SS / 2);
    const uint32_t* vlb = g_vtl + (size_t)bh * DD * (SS / 2);

    const int ro = ((lane >> 3) & 1) * 8 + (lane & 7);
    const int wo = (lane >> 4) * 4;

    float acc[2][8][4];
#pragma unroll
    for (int i = 0; i < 2; i++)
#pragma unroll
        for (int j = 0; j < 8; j++)
#pragma unroll
            for (int c = 0; c < 4; c++) acc[i][j][c] = 0.0f;

    auto load_stage = [&](int st, int kc) {
        const int w0 = kc * 16;
#pragma unroll
        for (int i = 0; i < 2; i++) {
            int idx = tid + i * 256;
            int row = idx >> 2, q4 = (idx & 3) * 4;
            cp16(smaddr(&Ah[st][row][q4]), ahb + (size_t)row * (SS / 2) + w0 + q4);
            cp16(smaddr(&Al[st][row][q4]), alb + (size_t)row * (SS / 2) + w0 + q4);
            cp16(smaddr(&Bh[st][row][q4]), vhb + (size_t)row * (SS / 2) + w0 + q4);
            cp16(smaddr(&Bl[st][row][q4]), vlb + (size_t)row * (SS / 2) + w0 + q4);
        }
    };

    load_stage(0, 0);
    CP_COMMIT;

#pragma unroll 1
    for (int kc = 0; kc < 64; kc++) {
        const int C = kc & 1;
        if (kc < 63) load_stage(C ^ 1, kc + 1);
        CP_COMMIT;
        if (kc < 63) { CP_WAIT1; } else { CP_WAIT0; }
        __syncthreads();

#pragma unroll
        for (int ks = 0; ks < 2; ks++) {
            const int ko = ks * 8;
            uint32_t ah[2][4], al[2][4];
#pragma unroll
            for (int mt = 0; mt < 2; mt++) {
                int r = wm * 32 + mt * 16 + ro;
                ldsm4(ah[mt][0], ah[mt][1], ah[mt][2], ah[mt][3], smaddr(&Ah[C][r][ko + wo]));
                ldsm4(al[mt][0], al[mt][1], al[mt][2], al[mt][3], smaddr(&Al[C][r][ko + wo]));
            }
#pragma unroll
            for (int np = 0; np < 4; np++) {
                int nr = wn * 64 + np * 16 + ro;
                uint32_t b0, b1, b2, b3, c0, c1, c2, c3;
                ldsm4(b0, b1, b2, b3, smaddr(&Bh[C][nr][ko + wo]));
                ldsm4(c0, c1, c2, c3, smaddr(&Bl[C][nr][ko + wo]));
#pragma unroll
                for (int mt = 0; mt < 2; mt++) {
                    MMA16816(acc[mt][np * 2],     ah[mt], b0, b2);
                    MMA16816(acc[mt][np * 2],     ah[mt], c0, c2);
                    MMA16816(acc[mt][np * 2],     al[mt], b0, b2);
                    MMA16816(acc[mt][np * 2 + 1], ah[mt], b1, b3);
                    MMA16816(acc[mt][np * 2 + 1], ah[mt], c1, c3);
                    MMA16816(acc[mt][np * 2 + 1], al[mt], b1, b3);
                }
            }
        }
        __syncthreads();
    }

    float* ob = out + (size_t)bh * SS * DD;
#pragma unroll
    for (int mt = 0; mt < 2; mt++) {
#pragma unroll
        for (int nt = 0; nt < 8; nt++) {
            int col  = wn * 64 + nt * 8 + 2 * t;
            int row0 = m_base + wm * 32 + mt * 16 + g;
#pragma unroll
            for (int half = 0; half < 2; half++) {
                int row = row0 + half * 8;
                *reinterpret_cast<float2*>(ob + (size_t)row * DD + col) =
                    make_float2(acc[mt][nt][half * 2], acc[mt][nt][half * 2 + 1]);
            }
        }
    }
}

// ---------------------------------------------------------------------------
// Launch
// ---------------------------------------------------------------------------
extern "C" void kernel_launch(void* const* d_in, const int* in_sizes, int n_in,
                              void* d_out, int out_size)
{
    const float* q    = (const float*)d_in[0];
    const float* k    = (const float*)d_in[1];
    const float* v    = (const float*)d_in[2];
    const int*   mask = (const int*)  d_in[3];
    const float* bias = (const float*)d_in[4];

    float* out  = (float*)d_out;                       // [B,H,S,D]
    float* attn = out + (size_t)BB * HH * SS * DD;     // [B,H,S,S]

    cudaFuncSetAttribute(sdpa_scores2_kernel,
                         cudaFuncAttributeMaxDynamicSharedMemorySize, 81920);
    cudaFuncSetAttribute(sdpa_out3_kernel,
                         cudaFuncAttributeMaxDynamicSharedMemorySize, 81920);

    split_qk_kernel<<<2048, 256>>>((const float4*)q, (const float4*)k);
    split_vt_kernel<<<dim3(SS / 64, BH), 256>>>(v);

    dim3 g1(SS / 128, SS / 128, BH);
    sdpa_scores2_kernel<<<g1, 256, 81920>>>(mask, bias, attn);

    sdpa_softmax_kernel<<<BH * SS, 256>>>(attn);

    dim3 g3(1, SS / 128, BH);
    sdpa_out3_kernel<<<g3, 256, 81920>>>(attn == nullptr ? nullptr : out);
}

// round 15
// speedup vs baseline: 1.2935x; 1.0549x over previous
#include <cuda_runtime.h>
#include <cuda_bf16.h>
#include <cstdint>

// Problem constants
#define BB 2
#define HH 16
#define SS 2048
#define DD 128
#define BH (BB*HH)

// ---------------------------------------------------------------------------
// Scratch: precomputed bf16 hi/lo splits (packed k-pairs in uint32 words)
//   g_qh/g_ql, g_kh/g_kl : [bh][s][64 words]   (q pre-scaled by 1/sqrt(D))
//   g_vth/g_vtl          : [bh][d][1024 words] (V transposed, k-major)
// ---------------------------------------------------------------------------
__device__ uint32_t g_qh[(size_t)BH*SS*64];
__device__ uint32_t g_ql[(size_t)BH*SS*64];
__device__ uint32_t g_kh[(size_t)BH*SS*64];
__device__ uint32_t g_kl[(size_t)BH*SS*64];
__device__ uint32_t g_vth[(size_t)BH*DD*(SS/2)];
__device__ uint32_t g_vtl[(size_t)BH*DD*(SS/2)];

// ---------------------------------------------------------------------------
// Helpers
// ---------------------------------------------------------------------------
__device__ __forceinline__ uint32_t pack_bf16(__nv_bfloat16 lo16, __nv_bfloat16 hi16) {
    __nv_bfloat162 t; t.x = lo16; t.y = hi16;
    return *reinterpret_cast<uint32_t*>(&t);
}

__device__ __forceinline__ void cvt_pair(float x, float y, uint32_t& whi, uint32_t& wlo) {
    __nv_bfloat16 hx = __float2bfloat16_rn(x);
    __nv_bfloat16 hy = __float2bfloat16_rn(y);
    float fx = __bfloat162float(hx);
    float fy = __bfloat162float(hy);
    whi = pack_bf16(hx, hy);
    wlo = pack_bf16(__float2bfloat16_rn(x - fx), __float2bfloat16_rn(y - fy));
}

__device__ __forceinline__ uint32_t smaddr(const void* p) {
    return static_cast<uint32_t>(__cvta_generic_to_shared(p));
}

#define MMA16816(C, A, B0, B1)                                                  \
    asm volatile(                                                               \
        "mma.sync.aligned.m16n8k16.row.col.f32.bf16.bf16.f32 "                  \
        "{%0,%1,%2,%3}, {%4,%5,%6,%7}, {%8,%9}, {%0,%1,%2,%3};"                 \
        : "+f"((C)[0]), "+f"((C)[1]), "+f"((C)[2]), "+f"((C)[3])                \
        : "r"((A)[0]), "r"((A)[1]), "r"((A)[2]), "r"((A)[3]),                   \
          "r"(B0), "r"(B1))

__device__ __forceinline__ void ldsm4(uint32_t& r0, uint32_t& r1, uint32_t& r2,
                                      uint32_t& r3, uint32_t addr) {
    asm volatile("ldmatrix.sync.aligned.m8n8.x4.shared.b16 {%0,%1,%2,%3}, [%4];"
                 : "=r"(r0), "=r"(r1), "=r"(r2), "=r"(r3) : "r"(addr));
}

__device__ __forceinline__ void cp16(uint32_t s, const void* g) {
    asm volatile("cp.async.cg.shared.global [%0], [%1], 16;" :: "r"(s), "l"(g) : "memory");
}
#define CP_COMMIT asm volatile("cp.async.commit_group;" ::: "memory")
#define CP_WAIT1  asm volatile("cp.async.wait_group 1;" ::: "memory")
#define CP_WAIT0  asm volatile("cp.async.wait_group 0;" ::: "memory")

// ---------------------------------------------------------------------------
// Precompute 1: split Q (scaled) and K into bf16 hi/lo packed words
// ---------------------------------------------------------------------------
__global__ __launch_bounds__(256)
void split_qk_kernel(const float4* __restrict__ q, const float4* __restrict__ k)
{
    const float scl = 0.08838834764831845f;  // 1/sqrt(128)
    const size_t N4 = (size_t)BH * SS * (DD / 4);
    const size_t stride = (size_t)gridDim.x * blockDim.x;
    for (size_t i = (size_t)blockIdx.x * blockDim.x + threadIdx.x; i < N4; i += stride) {
        uint32_t h0, l0, h1, l1;
        float4 a = q[i];
        cvt_pair(a.x * scl, a.y * scl, h0, l0);
        cvt_pair(a.z * scl, a.w * scl, h1, l1);
        g_qh[2 * i] = h0; g_qh[2 * i + 1] = h1;
        g_ql[2 * i] = l0; g_ql[2 * i + 1] = l1;
        float4 c = k[i];
        cvt_pair(c.x, c.y, h0, l0);
        cvt_pair(c.z, c.w, h1, l1);
        g_kh[2 * i] = h0; g_kh[2 * i + 1] = h1;
        g_kl[2 * i] = l0; g_kl[2 * i + 1] = l1;
    }
}

// ---------------------------------------------------------------------------
// Precompute 2: V -> transposed split (k-major per head-dim row)
// ---------------------------------------------------------------------------
__global__ __launch_bounds__(256)
void split_vt_kernel(const float* __restrict__ v)
{
    __shared__ float tile[64][133];
    const int bh = blockIdx.y;
    const int s0 = blockIdx.x * 64;
    const int tid = threadIdx.x;
    const float* vb = v + (size_t)bh * SS * DD + (size_t)s0 * DD;

#pragma unroll
    for (int i = 0; i < 8; i++) {
        int idx = tid + i * 256;
        int r = idx >> 5, c4 = (idx & 31) * 4;
        float4 x = *reinterpret_cast<const float4*>(vb + (size_t)r * DD + c4);
        tile[r][c4 + 0] = x.x; tile[r][c4 + 1] = x.y;
        tile[r][c4 + 2] = x.z; tile[r][c4 + 3] = x.w;
    }
    __syncthreads();

    uint32_t* vh = g_vth + (size_t)bh * DD * (SS / 2) + (s0 >> 1);
    uint32_t* vl = g_vtl + (size_t)bh * DD * (SS / 2) + (s0 >> 1);
#pragma unroll
    for (int i = 0; i < 16; i++) {
        int idx = tid + i * 256;
        int d = idx >> 5, w = idx & 31;
        uint32_t hw_, lw_;
        cvt_pair(tile[2 * w][d], tile[2 * w + 1][d], hw_, lw_);
        vh[(size_t)d * (SS / 2) + w] = hw_;
        vl[(size_t)d * (SS / 2) + w] = lw_;
    }
}

// ---------------------------------------------------------------------------
// Kernel 1: raw masked scores -> attn buffer
// 128x128 tile, 256 threads, k-chunk=32, 2-stage cp.async pipeline, ldmatrix.
// z-order: z = 2h + b so adjacent slabs share rel_bias[h] in L2.
// ---------------------------------------------------------------------------
__global__ __launch_bounds__(256, 2)
void sdpa_scores2_kernel(const int* __restrict__ mask, const float* __restrict__ bias,
                         float* __restrict__ attn)
{
    extern __shared__ uint32_t sm[];
    uint32_t (*Qh)[128][20] = reinterpret_cast<uint32_t(*)[128][20]>(sm);
    uint32_t (*Ql)[128][20] = reinterpret_cast<uint32_t(*)[128][20]>(sm + 5120);
    uint32_t (*Kh)[128][20] = reinterpret_cast<uint32_t(*)[128][20]>(sm + 10240);
    uint32_t (*Kl)[128][20] = reinterpret_cast<uint32_t(*)[128][20]>(sm + 15360);

    const int tid  = threadIdx.x;
    const int warp = tid >> 5, lane = tid & 31;
    const int g = lane >> 2, t = lane & 3;
    const int wm = warp & 3, wn = warp >> 2;
    const int z = blockIdx.z, h = z >> 1, b = z & 1, bh = b * HH + h;
    const int m_base = blockIdx.y * 128;
    const int n_base = blockIdx.x * 128;

    const uint32_t* qh = g_qh + (size_t)bh * SS * 64;
    const uint32_t* ql = g_ql + (size_t)bh * SS * 64;
    const uint32_t* kh = g_kh + (size_t)bh * SS * 64;
    const uint32_t* kl = g_kl + (size_t)bh * SS * 64;

    const int ro = ((lane >> 3) & 1) * 8 + (lane & 7);
    const int wo = (lane >> 4) * 4;

    float acc[2][8][4];
#pragma unroll
    for (int i = 0; i < 2; i++)
#pragma unroll
        for (int j = 0; j < 8; j++)
#pragma unroll
            for (int c = 0; c < 4; c++) acc[i][j][c] = 0.0f;

    auto load_stage = [&](int st, int kc) {
        const int w0 = kc * 16;
#pragma unroll
        for (int i = 0; i < 2; i++) {
            int idx = tid + i * 256;
            int row = idx >> 2, q4 = (idx & 3) * 4;
            cp16(smaddr(&Qh[st][row][q4]), qh + (size_t)(m_base + row) * 64 + w0 + q4);
            cp16(smaddr(&Ql[st][row][q4]), ql + (size_t)(m_base + row) * 64 + w0 + q4);
            cp16(smaddr(&Kh[st][row][q4]), kh + (size_t)(n_base + row) * 64 + w0 + q4);
            cp16(smaddr(&Kl[st][row][q4]), kl + (size_t)(n_base + row) * 64 + w0 + q4);
        }
    };

    load_stage(0, 0);
    CP_COMMIT;

#pragma unroll 1
    for (int kc = 0; kc < 4; kc++) {
        const int C = kc & 1;
        if (kc < 3) load_stage(C ^ 1, kc + 1);
        CP_COMMIT;
        if (kc < 3) { CP_WAIT1; } else { CP_WAIT0; }
        __syncthreads();

#pragma unroll
        for (int ks = 0; ks < 2; ks++) {
            const int ko = ks * 8;
            uint32_t ah[2][4], al[2][4];
#pragma unroll
            for (int mt = 0; mt < 2; mt++) {
                int r = wm * 32 + mt * 16 + ro;
                ldsm4(ah[mt][0], ah[mt][1], ah[mt][2], ah[mt][3], smaddr(&Qh[C][r][ko + wo]));
                ldsm4(al[mt][0], al[mt][1], al[mt][2], al[mt][3], smaddr(&Ql[C][r][ko + wo]));
            }
#pragma unroll
            for (int np = 0; np < 4; np++) {
                int nr = wn * 64 + np * 16 + ro;
                uint32_t b0, b1, b2, b3, c0, c1, c2, c3;
                ldsm4(b0, b1, b2, b3, smaddr(&Kh[C][nr][ko + wo]));
                ldsm4(c0, c1, c2, c3, smaddr(&Kl[C][nr][ko + wo]));
#pragma unroll
                for (int mt = 0; mt < 2; mt++) {
                    MMA16816(acc[mt][np * 2],     ah[mt], b0, b2);
                    MMA16816(acc[mt][np * 2],     ah[mt], c0, c2);
                    MMA16816(acc[mt][np * 2],     al[mt], b0, b2);
                    MMA16816(acc[mt][np * 2 + 1], ah[mt], b1, b3);
                    MMA16816(acc[mt][np * 2 + 1], ah[mt], c1, c3);
                    MMA16816(acc[mt][np * 2 + 1], al[mt], b1, b3);
                }
            }
        }
        __syncthreads();
    }

    // --- epilogue: + bias, mask, write raw scores (q was pre-scaled) ---
    const float* biasb = bias + (size_t)h * SS * SS;
    const int*   maskb = mask + (size_t)b * SS * SS;
    float*       attnb = attn + (size_t)bh * SS * SS;

#pragma unroll
    for (int mt = 0; mt < 2; mt++) {
#pragma unroll
        for (int nt = 0; nt < 8; nt++) {
            int col  = n_base + wn * 64 + nt * 8 + 2 * t;
            int row0 = m_base + wm * 32 + mt * 16 + g;
#pragma unroll
            for (int half = 0; half < 2; half++) {
                int row = row0 + half * 8;
                float2 bb = *reinterpret_cast<const float2*>(biasb + (size_t)row * SS + col);
                int2   mm = *reinterpret_cast<const int2*>(maskb + (size_t)row * SS + col);
                float s0 = acc[mt][nt][half * 2 + 0] + bb.x;
                float s1 = acc[mt][nt][half * 2 + 1] + bb.y;
                if (mm.x == 0) s0 = -1e9f;
                if (mm.y == 0) s1 = -1e9f;
                *reinterpret_cast<float2*>(attnb + (size_t)row * SS + col) = make_float2(s0, s1);
            }
        }
    }
}

// ---------------------------------------------------------------------------
// Kernel 2 (fused softmax + out): per CTA = 128-row slab x D=128 of one bh.
// Phase 1: stream raw scores slab, compute rowM/rowInv (max pass + sum pass,
//          sum pass L1-hot).
// Phase 2: out2-style mainloop over 64 k32 chunks; per chunk the staged raw
//          scores are normalized (exp * inv), written back to the attn buffer
//          (required output) and split to bf16 hi/lo for the MMA against the
//          pre-split V.
// ---------------------------------------------------------------------------
__global__ __launch_bounds__(256, 2)
void sdpa_softmax_out_kernel(float* __restrict__ attn, float* __restrict__ out)
{
    extern __shared__ uint32_t sm[];
    float    (*Ar)[128][36] = reinterpret_cast<float(*)[128][36]>(sm);        // 9216 w
    uint32_t (*Ah)[20]      = reinterpret_cast<uint32_t(*)[20]>(sm + 9216);   // 2560 w
    uint32_t (*Al)[20]      = reinterpret_cast<uint32_t(*)[20]>(sm + 11776);  // 2560 w
    uint32_t (*Bh)[128][20] = reinterpret_cast<uint32_t(*)[128][20]>(sm + 14336); // 5120 w
    uint32_t (*Bl)[128][20] = reinterpret_cast<uint32_t(*)[128][20]>(sm + 19456); // 5120 w
    float* rowM   = reinterpret_cast<float*>(sm + 24576);  // [128]
    float* rowInv = reinterpret_cast<float*>(sm + 24704);  // [128]

    const int tid  = threadIdx.x;
    const int warp = tid >> 5, lane = tid & 31;
    const int g = lane >> 2, t = lane & 3;
    const int wm = warp & 3, wn = warp >> 2;
    const int bh = blockIdx.y;
    const int m_base = blockIdx.x * 128;

    float* attnb = attn + (size_t)bh * SS * SS;   // raw scores in, normalized out
    const uint32_t* vhb = g_vth + (size_t)bh * DD * (SS / 2);
    const uint32_t* vlb = g_vtl + (size_t)bh * DD * (SS / 2);

    // ---------------- Phase 1: row max + row sum ----------------
#pragma unroll 1
    for (int i = 0; i < 16; i++) {
        int r = warp * 16 + i;                    // local row 0..127
        const float4* rp = reinterpret_cast<const float4*>(attnb + (size_t)(m_base + r) * SS);
        float m = -INFINITY;
#pragma unroll
        for (int j = 0; j < 16; j++) {
            float4 x = rp[lane + j * 32];
            m = fmaxf(m, fmaxf(fmaxf(x.x, x.y), fmaxf(x.z, x.w)));
        }
#pragma unroll
        for (int o = 16; o > 0; o >>= 1) m = fmaxf(m, __shfl_xor_sync(0xFFFFFFFFu, m, o));
        float s = 0.0f;
#pragma unroll
        for (int j = 0; j < 16; j++) {
            float4 x = rp[lane + j * 32];         // L1-hot re-read
            s += __expf(x.x - m) + __expf(x.y - m) + __expf(x.z - m) + __expf(x.w - m);
        }
#pragma unroll
        for (int o = 16; o > 0; o >>= 1) s += __shfl_xor_sync(0xFFFFFFFFu, s, o);
        if (lane == 0) { rowM[r] = m; rowInv[r] = 1.0f / s; }
    }
    __syncthreads();

    // ---------------- Phase 2: normalize + write + MMA ----------------
    const int ro = ((lane >> 3) & 1) * 8 + (lane & 7);
    const int wo = (lane >> 4) * 4;

    float acc[2][8][4];
#pragma unroll
    for (int i = 0; i < 2; i++)
#pragma unroll
        for (int j = 0; j < 8; j++)
#pragma unroll
            for (int c = 0; c < 4; c++) acc[i][j][c] = 0.0f;

    auto load_stage = [&](int st, int kc) {
        // raw scores: 128 rows x 8 float4
#pragma unroll
        for (int i = 0; i < 4; i++) {
            int idx = tid + i * 256;
            int row = idx >> 3, f4 = (idx & 7) * 4;
            cp16(smaddr(&Ar[st][row][f4]), attnb + (size_t)(m_base + row) * SS + kc * 32 + f4);
        }
        // V split tiles: 128 d-rows x 4 uint4 each (hi + lo)
#pragma unroll
        for (int i = 0; i < 2; i++) {
            int idx = tid + i * 256;
            int d = idx >> 2, q4 = (idx & 3) * 4;
            cp16(smaddr(&Bh[st][d][q4]), vhb + (size_t)d * (SS / 2) + kc * 16 + q4);
            cp16(smaddr(&Bl[st][d][q4]), vlb + (size_t)d * (SS / 2) + kc * 16 + q4);
        }
    };

    load_stage(0, 0);
    CP_COMMIT;

#pragma unroll 1
    for (int kc = 0; kc < 64; kc++) {
        const int C = kc & 1;
        if (kc < 63) load_stage(C ^ 1, kc + 1);
        CP_COMMIT;
        if (kc < 63) { CP_WAIT1; } else { CP_WAIT0; }
        __syncthreads();

        // normalize: e = exp(x - m) * inv; write required fp32 attn; split for MMA
#pragma unroll
        for (int i = 0; i < 4; i++) {
            int idx = tid + i * 256;
            int row = idx >> 3, f4 = idx & 7;
            float4 x = *reinterpret_cast<const float4*>(&Ar[C][row][f4 * 4]);
            float m = rowM[row], inv = rowInv[row];
            float4 e;
            e.x = __expf(x.x - m) * inv;
            e.y = __expf(x.y - m) * inv;
            e.z = __expf(x.z - m) * inv;
            e.w = __expf(x.w - m) * inv;
            *reinterpret_cast<float4*>(attnb + (size_t)(m_base + row) * SS + kc * 32 + f4 * 4) = e;
            uint32_t h0, l0, h1, l1;
            cvt_pair(e.x, e.y, h0, l0);
            cvt_pair(e.z, e.w, h1, l1);
            *reinterpret_cast<uint2*>(&Ah[row][f4 * 2]) = make_uint2(h0, h1);
            *reinterpret_cast<uint2*>(&Al[row][f4 * 2]) = make_uint2(l0, l1);
        }
        __syncthreads();

#pragma unroll
        for (int ks = 0; ks < 2; ks++) {
            const int ko = ks * 8;
            uint32_t ah[2][4], al[2][4];
#pragma unroll
            for (int mt = 0; mt < 2; mt++) {
                int r = wm * 32 + mt * 16 + ro;
                ldsm4(ah[mt][0], ah[mt][1], ah[mt][2], ah[mt][3], smaddr(&Ah[r][ko + wo]));
                ldsm4(al[mt][0], al[mt][1], al[mt][2], al[mt][3], smaddr(&Al[r][ko + wo]));
            }
#pragma unroll
            for (int np = 0; np < 4; np++) {
                int nr = wn * 64 + np * 16 + ro;
                uint32_t b0, b1, b2, b3, c0, c1, c2, c3;
                ldsm4(b0, b1, b2, b3, smaddr(&Bh[C][nr][ko + wo]));
                ldsm4(c0, c1, c2, c3, smaddr(&Bl[C][nr][ko + wo]));
#pragma unroll
                for (int mt = 0; mt < 2; mt++) {
                    MMA16816(acc[mt][np * 2],     ah[mt], b0, b2);
                    MMA16816(acc[mt][np * 2],     ah[mt], c0, c2);
                    MMA16816(acc[mt][np * 2],     al[mt], b0, b2);
                    MMA16816(acc[mt][np * 2 + 1], ah[mt], b1, b3);
                    MMA16816(acc[mt][np * 2 + 1], ah[mt], c1, c3);
                    MMA16816(acc[mt][np * 2 + 1], al[mt], b1, b3);
                }
            }
        }
        __syncthreads();
    }

    float* ob = out + (size_t)bh * SS * DD;
#pragma unroll
    for (int mt = 0; mt < 2; mt++) {
#pragma unroll
        for (int nt = 0; nt < 8; nt++) {
            int col  = wn * 64 + nt * 8 + 2 * t;
            int row0 = m_base + wm * 32 + mt * 16 + g;
#pragma unroll
            for (int half = 0; half < 2; half++) {
                int row = row0 + half * 8;
                *reinterpret_cast<float2*>(ob + (size_t)row * DD + col) =
                    make_float2(acc[mt][nt][half * 2], acc[mt][nt][half * 2 + 1]);
            }
        }
    }
}

// ---------------------------------------------------------------------------
// Launch
// ---------------------------------------------------------------------------
extern "C" void kernel_launch(void* const* d_in, const int* in_sizes, int n_in,
                              void* d_out, int out_size)
{
    const float* q    = (const float*)d_in[0];
    const float* k    = (const float*)d_in[1];
    const float* v    = (const float*)d_in[2];
    const int*   mask = (const int*)  d_in[3];
    const float* bias = (const float*)d_in[4];

    float* out  = (float*)d_out;                       // [B,H,S,D]
    float* attn = out + (size_t)BB * HH * SS * DD;     // [B,H,S,S]

    cudaFuncSetAttribute(sdpa_scores2_kernel,
                         cudaFuncAttributeMaxDynamicSharedMemorySize, 81920);
    cudaFuncSetAttribute(sdpa_softmax_out_kernel,
                         cudaFuncAttributeMaxDynamicSharedMemorySize, 99328);

    split_qk_kernel<<<2048, 256>>>((const float4*)q, (const float4*)k);
    split_vt_kernel<<<dim3(SS / 64, BH), 256>>>(v);

    dim3 g1(SS / 128, SS / 128, BH);
    sdpa_scores2_kernel<<<g1, 256, 81920>>>(mask, bias, attn);

    dim3 g2(SS / 128, BH);
    sdpa_softmax_out_kernel<<<g2, 256, 99328>>>(attn, out);
}